// round 1
// baseline (speedup 1.0000x reference)
#include <cuda_runtime.h>
#include <cstddef>

// Problem constants (fixed shapes for this problem)
#define NN    100000
#define FIN   128
#define FHID  128
#define FOUT  64

// ---------------- scratch (static __device__ per harness rules) ------------
__device__ int   g_deg[NN];
__device__ float g_dis[NN];
__device__ __align__(128) float g_h1s [(size_t)NN * FHID];   // dis[i] * (x@W1)
__device__ __align__(128) float g_acc1[(size_t)NN * FHID];   // scattered messages, layer 1
__device__ __align__(128) float g_h2s [(size_t)NN * FOUT];   // dis[i] * (h1f@W2)

// ---------------- init: zero acc1, zero d_out, deg=1 (self loop) -----------
__global__ void init_kernel(float4* __restrict__ out4, int M) {
    int t = blockIdx.x * blockDim.x + threadIdx.x;
    const int total4 = M * (FHID / 4);
    float4 z = make_float4(0.f, 0.f, 0.f, 0.f);
    if (t < total4) {
        ((float4*)g_acc1)[t] = z;
        if (t < M * (FOUT / 4)) out4[t] = z;
        if (t < M) g_deg[t] = 1;
    }
}

// ---------------- degree count at targets ----------------------------------
__global__ void degree_kernel(const int* __restrict__ col, int E) {
    int t = blockIdx.x * blockDim.x + threadIdx.x;
    if (t < E) atomicAdd(&g_deg[col[t]], 1);
}

__global__ void dis_kernel(int M) {
    int t = blockIdx.x * blockDim.x + threadIdx.x;
    if (t < M) g_dis[t] = rsqrtf((float)g_deg[t]);
}

// ---------------- register-blocked SGEMM with fused epilogues --------------
// C[i][:] = dis[i] * (Aeff[i] @ W),  Aeff = A  (FUSE=false)
//                                     Aeff = relu(dis[i]*(A+Aacc) + bpre)  (FUSE=true)
// A is [M,128] row-major, W is [128,BN] row-major, single column block (N==BN).
template <int BN, int TN, bool FUSE>
__global__ void __launch_bounds__(256, 2)
gemm_kernel(const float* __restrict__ A,
            const float* __restrict__ Aacc,
            const float* __restrict__ W,
            const float* __restrict__ bpre,
            float* __restrict__ C,
            int M)
{
    constexpr int BM  = 128, BK = 16, TM = 8;
    constexpr int BMP = BM + 4;                 // pad to break store conflicts
    __shared__ float As[BK][BMP];
    __shared__ float Bs[BK][BN];

    const int tid = threadIdx.x;
    const int tx  = tid & 15;                   // 0..15 col group
    const int ty  = tid >> 4;                   // 0..15 row group
    const int bm0 = blockIdx.x * BM;

    // A-tile load mapping: 128 rows x 16 k-cols, float4 per thread, 2 passes
    const int arow = tid >> 2;                  // 0..63
    const int acol = (tid & 3) << 2;            // 0,4,8,12

    // B-tile load mapping
    constexpr int BCOLS4 = BN / 4;              // 32 (BN=128) or 16 (BN=64)
    constexpr int BRPP   = 256 / BCOLS4;        // rows per pass: 8 or 16
    constexpr int BPASS  = BK / BRPP;           // 2 or 1
    const int brow = tid / BCOLS4;
    const int bcol = (tid % BCOLS4) << 2;

    float acc[TM][TN];
#pragma unroll
    for (int i = 0; i < TM; i++)
#pragma unroll
        for (int j = 0; j < TN; j++) acc[i][j] = 0.f;

    float dis_r[2] = {0.f, 0.f};
    if (FUSE) {
        int r0 = bm0 + arow, r1 = r0 + 64;
        if (r0 < M) dis_r[0] = g_dis[r0];
        if (r1 < M) dis_r[1] = g_dis[r1];
    }

    for (int kk = 0; kk < 128; kk += BK) {
        // --- load A tile (transposed into As[k][m]) ---
#pragma unroll
        for (int p = 0; p < 2; p++) {
            int r = bm0 + arow + p * 64;
            float4 v = make_float4(0.f, 0.f, 0.f, 0.f);
            if (r < M) {
                v = *(const float4*)(A + (size_t)r * 128 + kk + acol);
                if (FUSE) {
                    float4 va = *(const float4*)(Aacc + (size_t)r * 128 + kk + acol);
                    float4 vb = *(const float4*)(bpre + kk + acol);
                    float d = dis_r[p];
                    v.x = fmaxf(fmaf(d, v.x + va.x, vb.x), 0.f);
                    v.y = fmaxf(fmaf(d, v.y + va.y, vb.y), 0.f);
                    v.z = fmaxf(fmaf(d, v.z + va.z, vb.z), 0.f);
                    v.w = fmaxf(fmaf(d, v.w + va.w, vb.w), 0.f);
                }
            }
            As[acol + 0][arow + p * 64] = v.x;
            As[acol + 1][arow + p * 64] = v.y;
            As[acol + 2][arow + p * 64] = v.z;
            As[acol + 3][arow + p * 64] = v.w;
        }
        // --- load B tile ---
#pragma unroll
        for (int p = 0; p < BPASS; p++) {
            int kr = brow + p * BRPP;
            *(float4*)&Bs[kr][bcol] =
                *(const float4*)(W + (size_t)(kk + kr) * BN + bcol);
        }
        __syncthreads();

        // --- compute ---
#pragma unroll
        for (int k = 0; k < BK; k++) {
            float a[TM];
            float4 a0 = *(const float4*)&As[k][ty * TM];
            float4 a1 = *(const float4*)&As[k][ty * TM + 4];
            a[0] = a0.x; a[1] = a0.y; a[2] = a0.z; a[3] = a0.w;
            a[4] = a1.x; a[5] = a1.y; a[6] = a1.z; a[7] = a1.w;

            float b[TN];
            {
                float4 b0 = *(const float4*)&Bs[k][tx * TN];
                b[0] = b0.x; b[1] = b0.y; b[2] = b0.z; b[3] = b0.w;
                if (TN == 8) {
                    float4 b1v = *(const float4*)&Bs[k][tx * TN + 4];
                    b[4] = b1v.x; b[5] = b1v.y; b[6] = b1v.z; b[7] = b1v.w;
                }
            }
#pragma unroll
            for (int i = 0; i < TM; i++)
#pragma unroll
                for (int j = 0; j < TN; j++)
                    acc[i][j] = fmaf(a[i], b[j], acc[i][j]);
        }
        __syncthreads();
    }

    // --- epilogue: scale by dis[row], store ---
#pragma unroll
    for (int i = 0; i < TM; i++) {
        int r = bm0 + ty * TM + i;
        if (r < M) {
            float d = g_dis[r];
            float* cp = C + (size_t)r * BN + tx * TN;
            float4 o0;
            o0.x = acc[i][0] * d; o0.y = acc[i][1] * d;
            o0.z = acc[i][2] * d; o0.w = acc[i][3] * d;
            *(float4*)cp = o0;
            if (TN == 8) {
                float4 o1;
                o1.x = acc[i][4] * d; o1.y = acc[i][5] * d;
                o1.z = acc[i][6] * d; o1.w = acc[i][7] * d;
                *(float4*)(cp + 4) = o1;
            }
        }
    }
}

// ---------------- scatter layer 1: one warp per edge, 128 floats -----------
__global__ void scatter128_kernel(const int* __restrict__ rows,
                                  const int* __restrict__ cols, int E) {
    int gw   = (blockIdx.x * blockDim.x + threadIdx.x) >> 5;
    int lane = threadIdx.x & 31;
    if (gw >= E) return;
    int r = __ldg(rows + gw);
    int c = __ldg(cols + gw);
    float4 v = ((const float4*)(g_h1s + (size_t)r * 128))[lane];
    float* dst = g_acc1 + (size_t)c * 128 + lane * 4;
    asm volatile("red.global.add.v4.f32 [%0], {%1,%2,%3,%4};"
                 :: "l"(dst), "f"(v.x), "f"(v.y), "f"(v.z), "f"(v.w)
                 : "memory");
}

// ---------------- scatter layer 2: half-warp per edge, 64 floats -> d_out --
__global__ void scatter64_kernel(const int* __restrict__ rows,
                                 const int* __restrict__ cols,
                                 float* __restrict__ out, int E) {
    int gw   = (blockIdx.x * blockDim.x + threadIdx.x) >> 5;
    int lane = threadIdx.x & 31;
    int sub  = lane >> 4;          // 0/1 -> which edge of the pair
    int l16  = lane & 15;
    int e = gw * 2 + sub;
    if (e >= E) return;
    int r = __ldg(rows + e);
    int c = __ldg(cols + e);
    float4 v = ((const float4*)(g_h2s + (size_t)r * 64))[l16];
    float* dst = out + (size_t)c * 64 + l16 * 4;
    asm volatile("red.global.add.v4.f32 [%0], {%1,%2,%3,%4};"
                 :: "l"(dst), "f"(v.x), "f"(v.y), "f"(v.z), "f"(v.w)
                 : "memory");
}

// ---------------- final: out = dis[i]*(out + h2s) + b2 ---------------------
__global__ void final_kernel(float4* __restrict__ out4,
                             const float* __restrict__ b2, int M) {
    int t = blockIdx.x * blockDim.x + threadIdx.x;
    const int total4 = M * (FOUT / 4);
    if (t >= total4) return;
    int i  = t >> 4;     // node
    int j4 = t & 15;     // float4 index within 64 features
    float4 o = out4[t];
    float4 h = ((const float4*)g_h2s)[t];
    float4 b = ((const float4*)b2)[j4];
    float  d = g_dis[i];
    o.x = fmaf(d, o.x + h.x, b.x);
    o.y = fmaf(d, o.y + h.y, b.y);
    o.z = fmaf(d, o.z + h.z, b.z);
    o.w = fmaf(d, o.w + h.w, b.w);
    out4[t] = o;
}

// ---------------- launch ----------------------------------------------------
extern "C" void kernel_launch(void* const* d_in, const int* in_sizes, int n_in,
                              void* d_out, int out_size) {
    const float* x  = (const float*)d_in[0];   // [N,128]
    const int*   ei = (const int*)  d_in[1];   // [2,E]
    const float* W1 = (const float*)d_in[2];   // [128,128]
    const float* b1 = (const float*)d_in[3];   // [128]
    const float* W2 = (const float*)d_in[4];   // [128,64]
    const float* b2 = (const float*)d_in[5];   // [64]
    float* out = (float*)d_out;                // [N,64]

    const int M = in_sizes[0] / FIN;           // 100000
    const int E = in_sizes[1] / 2;             // 1600000
    const int* rows = ei;
    const int* cols = ei + E;

    float *h1s, *acc1, *h2s;
    cudaGetSymbolAddress((void**)&h1s,  g_h1s);
    cudaGetSymbolAddress((void**)&acc1, g_acc1);
    cudaGetSymbolAddress((void**)&h2s,  g_h2s);

    // 1) zero acc1 + d_out, deg = 1 (self loops)
    init_kernel<<<(M * 32 + 255) / 256, 256>>>((float4*)out, M);
    // 2) in-degree at targets
    degree_kernel<<<(E + 255) / 256, 256>>>(cols, E);
    // 3) dis = rsqrt(deg)
    dis_kernel<<<(M + 255) / 256, 256>>>(M);
    // 4) h1s = dis * (x @ W1)
    gemm_kernel<128, 8, false><<<(M + 127) / 128, 256>>>(x, nullptr, W1, nullptr, h1s, M);
    // 5) acc1[col] += h1s[row]   (one warp per edge)
    scatter128_kernel<<<(E + 7) / 8, 256>>>(rows, cols, E);
    // 6) h2s = dis * (relu(dis*(acc1+h1s)+b1) @ W2)   (epilogue fused into A load)
    gemm_kernel<64, 4, true><<<(M + 127) / 128, 256>>>(h1s, acc1, W2, b1, h2s, M);
    // 7) out[col] += h2s[row]    (two edges per warp)
    scatter64_kernel<<<(E + 15) / 16, 256>>>(rows, cols, out, E);
    // 8) out = dis*(out + h2s) + b2
    final_kernel<<<(M * 16 + 255) / 256, 256>>>((float4*)out, b2, M);
}

// round 2
// speedup vs baseline: 1.7210x; 1.7210x over previous
#include <cuda_runtime.h>
#include <cstddef>

#define NN    100000
#define FIN   128
#define FHID  128
#define FOUT  64
#define EMAX  1600000

// ---------------- static scratch ------------------------------------------
__device__ int   g_deg[NN];        // edge-only in-degree
__device__ int   g_offs[NN];       // CSR offsets (exclusive scan of g_deg)
__device__ int   g_cursor[NN];     // placement cursors
__device__ int   g_csr[EMAX];      // source node per CSR slot
__device__ float g_dis[NN];        // rsqrt(deg+1)
__device__ __align__(128) float g_h1s[(size_t)NN * FHID];  // dis*(x@W1)
__device__ __align__(128) float g_h1f[(size_t)NN * FHID];  // relu(dis*(agg+self)+b1)
__device__ __align__(128) float g_h2s[(size_t)NN * FOUT];  // dis*(h1f@W2)

// ---------------- degree --------------------------------------------------
__global__ void zero_deg_kernel(int M) {
    int t = blockIdx.x * blockDim.x + threadIdx.x;
    if (t < M) g_deg[t] = 0;
}
__global__ void degree_kernel(const int* __restrict__ col, int E) {
    int t = blockIdx.x * blockDim.x + threadIdx.x;
    if (t < E) atomicAdd(&g_deg[col[t]], 1);
}

// ---------------- 3-pass exclusive scan over g_deg (M ~ 100k) --------------
// pass1: per-1024-chunk sums (256 threads, 4 elems each)
__global__ void scan_pass1(int* __restrict__ bsum, int M) {
    __shared__ int sh[8];
    int b = blockIdx.x, t = threadIdx.x;
    int base = b * 1024;
    int v = 0;
#pragma unroll
    for (int k = 0; k < 4; k++) {
        int i = base + t + k * 256;
        if (i < M) v += g_deg[i];
    }
#pragma unroll
    for (int d = 16; d; d >>= 1) v += __shfl_down_sync(0xffffffffu, v, d);
    if ((t & 31) == 0) sh[t >> 5] = v;
    __syncthreads();
    if (t < 8) {
        int x = sh[t];
#pragma unroll
        for (int d = 4; d; d >>= 1) x += __shfl_down_sync(0xffu, x, d);
        if (t == 0) bsum[b] = x;
    }
}
// pass2: single-block exclusive scan of block sums (nb <= 1024)
__global__ void scan_pass2(int* __restrict__ bsum, int nb) {
    __shared__ int sh[1024];
    int t = threadIdx.x;
    sh[t] = (t < nb) ? bsum[t] : 0;
    __syncthreads();
    for (int d = 1; d < 1024; d <<= 1) {
        int x = (t >= d) ? sh[t - d] : 0;
        __syncthreads();
        sh[t] += x;
        __syncthreads();
    }
    int excl = (t == 0) ? 0 : sh[t - 1];
    if (t < nb) bsum[t] = excl;
}
// pass3: per-chunk exclusive scan + add chunk base; also dis, cursor init
__global__ void scan_pass3(const int* __restrict__ bsumExc, int M) {
    __shared__ int wsum[32];
    int t = threadIdx.x, b = blockIdx.x;
    int i = b * 1024 + t;
    int v = (i < M) ? g_deg[i] : 0;
    int lane = t & 31, wid = t >> 5;
    int inc = v;
#pragma unroll
    for (int d = 1; d < 32; d <<= 1) {
        int n = __shfl_up_sync(0xffffffffu, inc, d);
        if (lane >= d) inc += n;
    }
    if (lane == 31) wsum[wid] = inc;
    __syncthreads();
    if (wid == 0) {
        int x = wsum[lane];
        int ix = x;
#pragma unroll
        for (int d = 1; d < 32; d <<= 1) {
            int n = __shfl_up_sync(0xffffffffu, ix, d);
            if (lane >= d) ix += n;
        }
        wsum[lane] = ix - x;   // exclusive among warps
    }
    __syncthreads();
    if (i < M) {
        int excl = inc - v + wsum[wid] + bsumExc[b];
        g_offs[i]   = excl;
        g_cursor[i] = excl;
        g_dis[i]    = rsqrtf((float)(v + 1));   // +1 self loop
    }
}

// ---------------- CSR placement -------------------------------------------
__global__ void place_kernel(const int* __restrict__ rows,
                             const int* __restrict__ cols, int E) {
    int e = blockIdx.x * blockDim.x + threadIdx.x;
    if (e < E) {
        int c = cols[e];
        int p = atomicAdd(&g_cursor[c], 1);
        g_csr[p] = rows[e];
    }
}

// ---------------- register-blocked SGEMM, C = dis[i] * (A @ W) -------------
template <int BN, int TN>
__global__ void __launch_bounds__(256, 2)
gemm_kernel(const float* __restrict__ A,
            const float* __restrict__ W,
            float* __restrict__ C, int M)
{
    constexpr int BM = 128, BK = 16, TM = 8;
    constexpr int BMP = BM + 4;
    __shared__ float As[BK][BMP];
    __shared__ float Bs[BK][BN];

    const int tid = threadIdx.x;
    const int tx  = tid & 15;
    const int ty  = tid >> 4;
    const int bm0 = blockIdx.x * BM;

    const int arow = tid >> 2;
    const int acol = (tid & 3) << 2;

    constexpr int BCOLS4 = BN / 4;
    constexpr int BRPP   = 256 / BCOLS4;
    constexpr int BPASS  = BK / BRPP;
    const int brow = tid / BCOLS4;
    const int bcol = (tid % BCOLS4) << 2;

    float acc[TM][TN];
#pragma unroll
    for (int i = 0; i < TM; i++)
#pragma unroll
        for (int j = 0; j < TN; j++) acc[i][j] = 0.f;

    for (int kk = 0; kk < 128; kk += BK) {
#pragma unroll
        for (int p = 0; p < 2; p++) {
            int r = bm0 + arow + p * 64;
            float4 v = make_float4(0.f, 0.f, 0.f, 0.f);
            if (r < M) v = *(const float4*)(A + (size_t)r * 128 + kk + acol);
            As[acol + 0][arow + p * 64] = v.x;
            As[acol + 1][arow + p * 64] = v.y;
            As[acol + 2][arow + p * 64] = v.z;
            As[acol + 3][arow + p * 64] = v.w;
        }
#pragma unroll
        for (int p = 0; p < BPASS; p++) {
            int kr = brow + p * BRPP;
            *(float4*)&Bs[kr][bcol] =
                *(const float4*)(W + (size_t)(kk + kr) * BN + bcol);
        }
        __syncthreads();

#pragma unroll
        for (int k = 0; k < BK; k++) {
            float a[TM];
            float4 a0 = *(const float4*)&As[k][ty * TM];
            float4 a1 = *(const float4*)&As[k][ty * TM + 4];
            a[0] = a0.x; a[1] = a0.y; a[2] = a0.z; a[3] = a0.w;
            a[4] = a1.x; a[5] = a1.y; a[6] = a1.z; a[7] = a1.w;

            float b[TN];
            {
                float4 b0 = *(const float4*)&Bs[k][tx * TN];
                b[0] = b0.x; b[1] = b0.y; b[2] = b0.z; b[3] = b0.w;
                if (TN == 8) {
                    float4 b1v = *(const float4*)&Bs[k][tx * TN + 4];
                    b[4] = b1v.x; b[5] = b1v.y; b[6] = b1v.z; b[7] = b1v.w;
                }
            }
#pragma unroll
            for (int i = 0; i < TM; i++)
#pragma unroll
                for (int j = 0; j < TN; j++)
                    acc[i][j] = fmaf(a[i], b[j], acc[i][j]);
        }
        __syncthreads();
    }

#pragma unroll
    for (int i = 0; i < TM; i++) {
        int r = bm0 + ty * TM + i;
        if (r < M) {
            float d = g_dis[r];
            float* cp = C + (size_t)r * BN + tx * TN;
            float4 o0;
            o0.x = acc[i][0] * d; o0.y = acc[i][1] * d;
            o0.z = acc[i][2] * d; o0.w = acc[i][3] * d;
            *(float4*)cp = o0;
            if (TN == 8) {
                float4 o1;
                o1.x = acc[i][4] * d; o1.y = acc[i][5] * d;
                o1.z = acc[i][6] * d; o1.w = acc[i][7] * d;
                *(float4*)(cp + 4) = o1;
            }
        }
    }
}

// ------- agg1: warp/node, h1f = relu(dis*(sum_nbr h1s + h1s[self]) + b1) ---
__global__ void __launch_bounds__(256)
agg1_kernel(const float* __restrict__ b1, int M) {
    int w    = (blockIdx.x * 256 + threadIdx.x) >> 5;
    int lane = threadIdx.x & 31;
    if (w >= M) return;
    int beg = g_offs[w];
    int end = beg + g_deg[w];
    const float4* h = (const float4*)g_h1s;
    float4 s = __ldg(h + (size_t)w * 32 + lane);    // self term
    for (int j0 = beg; j0 < end; j0 += 32) {
        int rem = end - j0;
        int cnt = rem < 32 ? rem : 32;
        int myi = (lane < rem) ? __ldg(g_csr + j0 + lane) : 0;
        int j = 0;
        for (; j + 4 <= cnt; j += 4) {
            int s0 = __shfl_sync(0xffffffffu, myi, j);
            int s1 = __shfl_sync(0xffffffffu, myi, j + 1);
            int s2 = __shfl_sync(0xffffffffu, myi, j + 2);
            int s3 = __shfl_sync(0xffffffffu, myi, j + 3);
            float4 v0 = __ldg(h + (size_t)s0 * 32 + lane);
            float4 v1 = __ldg(h + (size_t)s1 * 32 + lane);
            float4 v2 = __ldg(h + (size_t)s2 * 32 + lane);
            float4 v3 = __ldg(h + (size_t)s3 * 32 + lane);
            s.x += (v0.x + v1.x) + (v2.x + v3.x);
            s.y += (v0.y + v1.y) + (v2.y + v3.y);
            s.z += (v0.z + v1.z) + (v2.z + v3.z);
            s.w += (v0.w + v1.w) + (v2.w + v3.w);
        }
        for (; j < cnt; j++) {
            int si = __shfl_sync(0xffffffffu, myi, j);
            float4 v = __ldg(h + (size_t)si * 32 + lane);
            s.x += v.x; s.y += v.y; s.z += v.z; s.w += v.w;
        }
    }
    float  d = g_dis[w];
    float4 b = __ldg((const float4*)b1 + lane);
    float4 o;
    o.x = fmaxf(fmaf(d, s.x, b.x), 0.f);
    o.y = fmaxf(fmaf(d, s.y, b.y), 0.f);
    o.z = fmaxf(fmaf(d, s.z, b.z), 0.f);
    o.w = fmaxf(fmaf(d, s.w, b.w), 0.f);
    ((float4*)g_h1f)[(size_t)w * 32 + lane] = o;
}

// ------- agg2: half-warp/node, out = dis*(sum_nbr h2s + h2s[self]) + b2 ----
__global__ void __launch_bounds__(256)
agg2_kernel(float* __restrict__ out, const float* __restrict__ b2, int M) {
    int tid  = blockIdx.x * 256 + threadIdx.x;
    int node = tid >> 4;
    int lane = threadIdx.x & 31;
    int l16  = lane & 15;
    unsigned mask = 0xFFFFu << (lane & 16);
    bool valid = node < M;
    int beg = 0, end = 0;
    if (valid) { beg = g_offs[node]; end = beg + g_deg[node]; }
    const float4* h = (const float4*)g_h2s;
    float4 s = valid ? __ldg(h + (size_t)node * 16 + l16)
                     : make_float4(0.f, 0.f, 0.f, 0.f);
    for (int j0 = beg; j0 < end; j0 += 16) {
        int rem = end - j0;
        int cnt = rem < 16 ? rem : 16;
        int myi = (l16 < rem) ? __ldg(g_csr + j0 + l16) : 0;
        int j = 0;
        for (; j + 4 <= cnt; j += 4) {
            int s0 = __shfl_sync(mask, myi, j,     16);
            int s1 = __shfl_sync(mask, myi, j + 1, 16);
            int s2 = __shfl_sync(mask, myi, j + 2, 16);
            int s3 = __shfl_sync(mask, myi, j + 3, 16);
            float4 v0 = __ldg(h + (size_t)s0 * 16 + l16);
            float4 v1 = __ldg(h + (size_t)s1 * 16 + l16);
            float4 v2 = __ldg(h + (size_t)s2 * 16 + l16);
            float4 v3 = __ldg(h + (size_t)s3 * 16 + l16);
            s.x += (v0.x + v1.x) + (v2.x + v3.x);
            s.y += (v0.y + v1.y) + (v2.y + v3.y);
            s.z += (v0.z + v1.z) + (v2.z + v3.z);
            s.w += (v0.w + v1.w) + (v2.w + v3.w);
        }
        for (; j < cnt; j++) {
            int si = __shfl_sync(mask, myi, j, 16);
            float4 v = __ldg(h + (size_t)si * 16 + l16);
            s.x += v.x; s.y += v.y; s.z += v.z; s.w += v.w;
        }
    }
    if (valid) {
        float  d = g_dis[node];
        float4 b = __ldg((const float4*)b2 + l16);
        float4 o;
        o.x = fmaf(d, s.x, b.x);
        o.y = fmaf(d, s.y, b.y);
        o.z = fmaf(d, s.z, b.z);
        o.w = fmaf(d, s.w, b.w);
        ((float4*)out)[(size_t)node * 16 + l16] = o;
    }
}

// ---------------- launch ----------------------------------------------------
__device__ int g_bsum[1024];

extern "C" void kernel_launch(void* const* d_in, const int* in_sizes, int n_in,
                              void* d_out, int out_size) {
    const float* x  = (const float*)d_in[0];
    const int*   ei = (const int*)  d_in[1];
    const float* W1 = (const float*)d_in[2];
    const float* b1 = (const float*)d_in[3];
    const float* W2 = (const float*)d_in[4];
    const float* b2 = (const float*)d_in[5];
    float* out = (float*)d_out;

    const int M = in_sizes[0] / FIN;
    const int E = in_sizes[1] / 2;
    const int* rows = ei;
    const int* cols = ei + E;

    float *h1s, *h1f, *h2s;
    int* bsum;
    cudaGetSymbolAddress((void**)&h1s,  g_h1s);
    cudaGetSymbolAddress((void**)&h1f,  g_h1f);
    cudaGetSymbolAddress((void**)&h2s,  g_h2s);
    cudaGetSymbolAddress((void**)&bsum, g_bsum);

    const int nb = (M + 1023) / 1024;

    // CSR build
    zero_deg_kernel<<<(M + 255) / 256, 256>>>(M);
    degree_kernel<<<(E + 255) / 256, 256>>>(cols, E);
    scan_pass1<<<nb, 256>>>(bsum, M);
    scan_pass2<<<1, 1024>>>(bsum, nb);
    scan_pass3<<<nb, 1024>>>(bsum, M);
    place_kernel<<<(E + 255) / 256, 256>>>(rows, cols, E);

    // layer 1
    gemm_kernel<128, 8><<<(M + 127) / 128, 256>>>(x, W1, h1s, M);
    agg1_kernel<<<(M * 32 + 255) / 256, 256>>>(b1, M);

    // layer 2
    gemm_kernel<64, 4><<<(M + 127) / 128, 256>>>(h1f, W2, h2s, M);
    agg2_kernel<<<(M * 16 + 255) / 256, 256>>>(out, b2, M);
}